// round 13
// baseline (speedup 1.0000x reference)
#include <cuda_runtime.h>
#include <math.h>

#define Bb 32
#define Tt 50
#define TS 49
#define Dd 100
#define G4 400
#define Kk 10

__device__ __align__(16) float g_WTa[3*Dd*Dd];
__device__ __align__(16) float g_WTl[Dd*Dd];
__device__ __align__(16) float g_WTf[2*Dd*Dd];
__device__ __align__(16) float g_WTih[Dd*G4];
__device__ __align__(16) float g_WThh[Dd*G4];
__device__ __align__(16) float g_bsum[G4];
__device__ __align__(16) float g_qvec[Dd];
__device__ __align__(16) float g_kvec[Dd];
__device__ float g_qkb[2];
__device__ __align__(16) float g_gx[Bb*TS*G4];
__device__ __align__(16) float g_qsv[Bb*TS*5*Dd];
__device__ float g_ql[Bb*TS*5];
__device__ int g_ti[Bb*TS*Kk];
__device__ unsigned g_sv[Bb*TS];

__device__ __forceinline__ float ftanh(float x){
    x = fminf(fmaxf(x, -15.0f), 15.0f);
    float e = __expf(-2.0f*x);
    return __fdividef(1.0f - e, 1.0f + e);
}
__device__ __forceinline__ float fsig(float x){
    return __fdividef(1.0f, 1.0f + __expf(-x));
}

__global__ void prep(const float* __restrict__ aggw, const float* __restrict__ Wal,
                     const float* __restrict__ Wfus, const float* __restrict__ Wih,
                     const float* __restrict__ Whh, const float* __restrict__ bih,
                     const float* __restrict__ bhh, const float* __restrict__ Wq,
                     const float* __restrict__ bq, const float* __restrict__ Wk,
                     const float* __restrict__ bk, const float* __restrict__ Ww)
{
    const int N0=3*Dd*Dd, N1=Dd*Dd, N2=2*Dd*Dd, N3=Dd*G4, N4=Dd*G4, N5=G4, N6=Dd, N7=Dd;
    const int total=N0+N1+N2+N3+N4+N5+N6+N7+2;
    // destination-linear indexing: coalesced writes, strided reads (hidden by MLP)
    for(int i=blockIdx.x*blockDim.x+threadIdx.x; i<total; i+=gridDim.x*blockDim.x){
        int x=i;
        if(x<N0){int j=x/(Dd*Dd);int r=x%(Dd*Dd);int k=r/Dd,d=r%Dd;
            g_WTa[x]=aggw[j*Dd*Dd+d*Dd+k]; continue;}
        x-=N0;
        if(x<N1){int k=x/Dd,d=x%Dd; g_WTl[x]=Wal[d*Dd+k]; continue;}
        x-=N1;
        if(x<N2){int k=x/Dd,d=x%Dd; g_WTf[x]=Wfus[d*2*Dd+k]; continue;}
        x-=N2;
        if(x<N3){int k=x/G4,j=x%G4; g_WTih[x]=Wih[j*Dd+k]; continue;}
        x-=N3;
        if(x<N4){int k=x/G4,j=x%G4; g_WThh[x]=Whh[j*Dd+k]; continue;}
        x-=N4;
        if(x<N5){ g_bsum[x]=bih[x]+bhh[x]; continue;}
        x-=N5;
        if(x<N6){ float a=0.f; for(int j=0;j<Dd;j++) a=fmaf(Wq[j*Dd+x],Ww[j],a);
            g_qvec[x]=a; continue;}
        x-=N6;
        if(x<N7){ float a=0.f; for(int j=0;j<Dd;j++) a=fmaf(Wk[j*Dd+x],Ww[Dd+j],a);
            g_kvec[x]=a; continue;}
        x-=N7;
        if(x==0){ float a=0.f; for(int j=0;j<Dd;j++) a=fmaf(bq[j],Ww[j],a); g_qkb[0]=a; }
        else    { float a=0.f; for(int j=0;j<Dd;j++) a=fmaf(bk[j],Ww[Dd+j],a); g_qkb[1]=a; }
    }
}

struct __align__(16) SB {
    float A2[36][104];
    float A1[6][104];
    float A0[104];
    float s0[104];
    float sT[Dd][8];
    int L1[8]; int L2[36]; int L3[40];
};
// dynamic smem: sW0|sW1|sW2 (30000 floats) then SB[2]
#define DYN_BYTES (30000*4 + 2*(int)sizeof(SB))

__device__ __forceinline__ void mv1(const float* s, const float* WT,
                                    const float* bias, float* dst, int lt)
{
    if(lt<Dd){
        float a=bias[lt];
        #pragma unroll 4
        for(int k=0;k<Dd;k++) a=fmaf(s[k],WT[k*Dd+lt],a);
        dst[lt]=ftanh(a);
    }
}

__device__ __forceinline__ void mv6(const float (*sT)[8], const float* WT,
                                    const float* bias, float (*dst)[104], int rb, int lt)
{
    if(lt<Dd){
        float bb=bias[lt];
        float a0=bb,a1=bb,a2=bb,a3=bb,a4=bb,a5=bb;
        #pragma unroll 4
        for(int k=0;k<Dd;k++){
            float w=WT[k*Dd+lt];
            float4 v=*(const float4*)&sT[k][0];
            float2 u=*(const float2*)&sT[k][4];
            a0=fmaf(v.x,w,a0); a1=fmaf(v.y,w,a1); a2=fmaf(v.z,w,a2);
            a3=fmaf(v.w,w,a3); a4=fmaf(u.x,w,a4); a5=fmaf(u.y,w,a5);
        }
        dst[rb+0][lt]=ftanh(a0); dst[rb+1][lt]=ftanh(a1); dst[rb+2][lt]=ftanh(a2);
        dst[rb+3][lt]=ftanh(a3); dst[rb+4][lt]=ftanh(a4); dst[rb+5][lt]=ftanh(a5);
    }
}

// One aggregation side; all 256 threads enter (barriers uniform). lt = tid&127.
// W0/W1/W2 are SHARED-memory staged copies.
__device__ void agg(int n0, const int* __restrict__ tA, const int* __restrict__ tB,
                    const float* __restrict__ Eev, const float* __restrict__ Eod,
                    const float* W0, const float* W1, const float* W2,
                    const float* __restrict__ aggb, const float* __restrict__ bal,
                    float* eout, SB* Bf, int lt)
{
    const float *b0=aggb, *b1=aggb+Dd, *b2=aggb+2*Dd;
    const float inv6=1.0f/6.0f;

    if(lt<6)  Bf->L1[lt]=tA[n0*6+lt];
    if(lt<Dd) Bf->A0[lt]=Eev[(long)n0*Dd+lt];
    __syncthreads();
    if(lt<36) Bf->L2[lt]=tB[Bf->L1[lt/6]*6+lt%6];
    #pragma unroll
    for(int r=0;r<6;r++) if(lt<Dd) Bf->A1[r][lt]=Eod[(long)Bf->L1[r]*Dd+lt];
    __syncthreads();
    for(int r=0;r<36;r++) if(lt<Dd) Bf->A2[r][lt]=Eev[(long)Bf->L2[r]*Dd+lt];
    __syncthreads();

    // i=0, j=0
    if(lt<Dd){ float ss=0.f;
        #pragma unroll
        for(int r=0;r<6;r++) ss+=Bf->A1[r][lt];
        Bf->s0[lt]=ss*inv6+Bf->A0[lt]; }
    __syncthreads(); mv1(Bf->s0,W0,b0,Bf->A0,lt); __syncthreads();
    // i=0, j=1
    for(int it=lt;it<600;it+=128){ int g=it/Dd,k=it-g*Dd; float ss=0.f;
        #pragma unroll
        for(int j=0;j<6;j++) ss+=Bf->A2[g*6+j][k];
        Bf->sT[k][g]=ss*inv6+Bf->A1[g][k]; }
    __syncthreads(); mv6(Bf->sT,W1,b1,Bf->A1,0,lt); __syncthreads();
    // i=0, j=2
    for(int g=0;g<6;g++){
        if(lt<36) Bf->L3[lt]=tA[Bf->L2[g*6+lt/6]*6+lt%6];
        __syncthreads();
        for(int it=lt;it<600;it+=128){ int r=it/Dd,k=it-r*Dd; float ss=0.f;
            #pragma unroll
            for(int j=0;j<6;j++) ss+=Eod[(long)Bf->L3[r*6+j]*Dd+k];
            Bf->sT[k][r]=ss*inv6+Bf->A2[g*6+r][k]; }
        __syncthreads(); mv6(Bf->sT,W2,b2,Bf->A2,g*6,lt); __syncthreads();
    }
    // i=1, j=0
    if(lt<Dd){ float ss=0.f;
        #pragma unroll
        for(int r=0;r<6;r++) ss+=Bf->A1[r][lt];
        Bf->s0[lt]=ss*inv6+Bf->A0[lt]; }
    __syncthreads(); mv1(Bf->s0,W0,b0,Bf->A0,lt); __syncthreads();
    // i=1, j=1
    for(int it=lt;it<600;it+=128){ int g=it/Dd,k=it-g*Dd; float ss=0.f;
        #pragma unroll
        for(int j=0;j<6;j++) ss+=Bf->A2[g*6+j][k];
        Bf->sT[k][g]=ss*inv6+Bf->A1[g][k]; }
    __syncthreads(); mv6(Bf->sT,W1,b1,Bf->A1,0,lt); __syncthreads();
    // i=2, j=0
    if(lt<Dd){ float ss=0.f;
        #pragma unroll
        for(int r=0;r<6;r++) ss+=Bf->A1[r][lt];
        Bf->s0[lt]=ss*inv6+Bf->A0[lt]; }
    __syncthreads(); mv1(Bf->s0,W0,b0,Bf->A0,lt); __syncthreads();
    // final projection (W_agg_last stays in global/L2 — single use)
    mv1(Bf->A0,g_WTl,bal,eout,lt); __syncthreads();
}

__global__ void __launch_bounds__(256) kA(
    const int* __restrict__ user, const int* __restrict__ question,
    const int* __restrict__ response, const int* __restrict__ mask,
    const int* __restrict__ qnb, const int* __restrict__ snb,
    const int* __restrict__ unb, const int* __restrict__ qnb2, const int* __restrict__ qsix,
    const float* __restrict__ Eq, const float* __restrict__ Eq2, const float* __restrict__ Es,
    const float* __restrict__ Eu, const float* __restrict__ Er,
    const float* __restrict__ w1q, const float* __restrict__ w2q,
    const float* __restrict__ aggb, const float* __restrict__ bal,
    const float* __restrict__ bfus)
{
    extern __shared__ __align__(16) float dyn[];
    float* sW0 = dyn;
    float* sW1 = dyn + Dd*Dd;
    float* sW2 = dyn + 2*Dd*Dd;
    SB* sbp = (SB*)(dyn + 3*Dd*Dd);

    __shared__ float e1s[104], e2s[104], eh[104], erv[104], etv[104];
    __shared__ __align__(16) float qss[5*Dd];
    __shared__ float sc[64];

    int t=blockIdx.x, b=blockIdx.y, tid=threadIdx.x;
    int side=tid>>7, lt=tid&127;
    int qt=question[b*Tt+t], ut=user[b*Tt+t], rt=response[b*Tt+t], m=mask[b*Tt+t];

    if(m==1){
        // stage agg weights into shared (coalesced float4 copy)
        {
            const float4* src=(const float4*)g_WTa;
            float4* dst=(float4*)dyn;
            #pragma unroll 4
            for(int i=tid;i<(3*Dd*Dd)/4;i+=256) dst[i]=src[i];
        }
        int n0            = side ? ut   : qt;
        const int* tA     = side ? unb  : qnb;
        const int* tB     = side ? qnb2 : snb;
        const float* Eev  = side ? Eu   : Eq;
        const float* Eod  = side ? Eq2  : Es;
        float* eo         = side ? e2s  : e1s;
        agg(n0,tA,tB,Eev,Eod,sW0,sW1,sW2,aggb,bal,eo,&sbp[side],lt);
    } else {
        if(tid<Dd){
            e1s[tid]=Eq[(long)qt*Dd+tid];
            e2s[tid]=Eq2[(long)qt*Dd+tid];
        }
    }
    __syncthreads();

    float w1=w1q[0], w2=w2q[0];
    if(tid<Dd){ eh[tid]=w1*e1s[tid]+w2*e2s[tid]; erv[tid]=Er[rt*Dd+tid]; }
    __syncthreads();
    if(tid<Dd){
        float a=bfus[tid];
        #pragma unroll 4
        for(int k=0;k<Dd;k++) a=fmaf(eh[k],g_WTf[k*Dd+tid],a);
        #pragma unroll 4
        for(int k=0;k<Dd;k++) a=fmaf(erv[k],g_WTf[(Dd+k)*Dd+tid],a);
        etv[tid]=fmaxf(a,0.0f);
    }
    __syncthreads();

    long bt=(long)b*TS+t;
    if(tid<200){
        float2 a0=*(const float2*)&g_bsum[2*tid];
        float2 a1=make_float2(0.f,0.f);
        #pragma unroll 4
        for(int k=0;k<Dd;k+=2){
            float2 w0=*(const float2*)&g_WTih[k*G4+2*tid];
            float2 w1v=*(const float2*)&g_WTih[(k+1)*G4+2*tid];
            float e0=etv[k], e1v=etv[k+1];
            a0.x=fmaf(e0,w0.x,a0.x); a0.y=fmaf(e0,w0.y,a0.y);
            a1.x=fmaf(e1v,w1v.x,a1.x); a1.y=fmaf(e1v,w1v.y,a1.y);
        }
        float2 r; r.x=a0.x+a1.x; r.y=a0.y+a1.y;
        *(float2*)&g_gx[bt*G4+2*tid]=r;
    }

    int qn=question[b*Tt+t+1];
    if(tid<Dd){
        qss[tid]=Eq[(long)qn*Dd+tid];
        #pragma unroll
        for(int q=1;q<5;q++){
            int sid=qsix[qn*4+(q-1)];
            qss[q*Dd+tid]=Es[(long)sid*Dd+tid];
        }
    }
    __syncthreads();
    for(int i=tid;i<5*Dd;i+=256) g_qsv[bt*5*Dd+i]=qss[i];
    if(tid<5){
        float a=g_qkb[0];
        #pragma unroll 4
        for(int d=0;d<Dd;d++) a=fmaf(qss[tid*Dd+d],g_qvec[d],a);
        g_ql[bt*5+tid]=a;
    }
    if(tid<t){
        int qj=question[b*Tt+tid];
        const float4* row=(const float4*)(Eq+(long)qj*Dd);
        float a=0.f;
        #pragma unroll 5
        for(int kk=0;kk<25;kk++){
            float4 r4=row[kk];
            a=fmaf(r4.x,qss[4*kk+0],a); a=fmaf(r4.y,qss[4*kk+1],a);
            a=fmaf(r4.z,qss[4*kk+2],a); a=fmaf(r4.w,qss[4*kk+3],a);
        }
        sc[tid]=a;
    }
    __syncthreads();
    if(tid==0){
        unsigned sv=1u;
        bool used[64];
        for(int j=0;j<t;j++) used[j]=false;
        for(int s=0;s<Kk;s++){
            float best=-3.4e38f; int bi=-1;
            for(int j=0;j<t;j++)
                if(!used[j] && sc[j]>best){ best=sc[j]; bi=j; }
            if(bi>=0){ used[bi]=true; g_ti[bt*Kk+s]=bi; sv|=(1u<<(s+1)); }
            else      { g_ti[bt*Kk+s]=0; }
        }
        g_sv[bt]=sv;
    }
}

__global__ void __launch_bounds__(256) kB(const int* __restrict__ mask,
                                          const float* __restrict__ bw_,
                                          float* __restrict__ out)
{
    __shared__ float h[104], c[104];
    __shared__ __align__(16) float gates[G4];
    __shared__ float sh[TS][Dd];
    __shared__ __align__(16) float qsl[5*Dd];
    __shared__ float gd[56], kl[12], qll[8], kv[104];
    __shared__ int il[12];
    __shared__ unsigned sv_s;

    int b=blockIdx.x, tid=threadIdx.x;
    if(tid<Dd){ h[tid]=0.f; c[tid]=0.f; kv[tid]=g_kvec[tid]; }
    if(tid==0) out[b*Tt]=0.5f;
    __syncthreads();
    float kb=g_qkb[1], bw=bw_[0];

    for(int t=0;t<TS;t++){
        long bt=(long)b*TS+t;
        // gates = gates_x + h @ W_hh^T  (200 threads x 2 outputs, 4 split chains)
        if(tid<200){
            float2 a0=*(const float2*)&g_gx[bt*G4+2*tid];
            float2 a1=make_float2(0.f,0.f);
            float2 a2=make_float2(0.f,0.f);
            float2 a3=make_float2(0.f,0.f);
            #pragma unroll 4
            for(int k=0;k<Dd;k+=4){
                float h0=h[k],h1=h[k+1],h2=h[k+2],h3=h[k+3];
                float2 w0=*(const float2*)&g_WThh[(k  )*G4+2*tid];
                float2 w1=*(const float2*)&g_WThh[(k+1)*G4+2*tid];
                float2 w2=*(const float2*)&g_WThh[(k+2)*G4+2*tid];
                float2 w3=*(const float2*)&g_WThh[(k+3)*G4+2*tid];
                a0.x=fmaf(h0,w0.x,a0.x); a0.y=fmaf(h0,w0.y,a0.y);
                a1.x=fmaf(h1,w1.x,a1.x); a1.y=fmaf(h1,w1.y,a1.y);
                a2.x=fmaf(h2,w2.x,a2.x); a2.y=fmaf(h2,w2.y,a2.y);
                a3.x=fmaf(h3,w3.x,a3.x); a3.y=fmaf(h3,w3.y,a3.y);
            }
            float2 r; r.x=(a0.x+a1.x)+(a2.x+a3.x); r.y=(a0.y+a1.y)+(a2.y+a3.y);
            *(float2*)&gates[2*tid]=r;
        }
        __syncthreads();
        if(tid<Dd){
            float gi=gates[tid], gf=gates[Dd+tid], gg=gates[2*Dd+tid], go=gates[3*Dd+tid];
            float c2=fsig(gf)*c[tid]+fsig(gi)*ftanh(gg);
            float h2=fsig(go)*ftanh(c2);
            if(mask[b*Tt+t]==1){ h[tid]=h2; c[tid]=c2; }
            sh[t][tid]=h[tid];
        }
        for(int i=tid;i<5*Dd;i+=256) qsl[i]=g_qsv[bt*5*Dd+i];
        if(tid>=128&&tid<138) il[tid-128]=g_ti[bt*Kk+tid-128];
        if(tid>=138&&tid<143) qll[tid-138]=g_ql[bt*5+tid-138];
        if(tid==143) sv_s=g_sv[bt];
        __syncthreads();
        if(tid<55){
            int q=tid/11, s=tid-q*11;
            const float* st=(s==0)?h:sh[il[s-1]];
            float a0=0.f,a1=0.f;
            #pragma unroll 2
            for(int d=0;d<Dd;d+=2){
                a0=fmaf(qsl[q*Dd+d],st[d],a0);
                a1=fmaf(qsl[q*Dd+d+1],st[d+1],a1);
            }
            gd[tid]=a0+a1;
        }
        if(tid>=64&&tid<75){
            int s=tid-64;
            const float* st=(s==0)?h:sh[il[s-1]];
            float a0=kb,a1=0.f;
            #pragma unroll 2
            for(int d=0;d<Dd;d+=2){
                a0=fmaf(st[d],kv[d],a0);
                a1=fmaf(st[d+1],kv[d+1],a1);
            }
            kl[s]=a0+a1;
        }
        __syncthreads();
        if(tid<32){
            unsigned sv=sv_s;
            int i0=tid, i1=tid+32;
            int q0=i0/11, s0=i0-q0*11;
            float l0=((sv>>s0)&1u)?(qll[q0]+kl[s0]+bw):(-1e30f);
            float l1=-1e30f;
            if(i1<55){ int q1=i1/11, s1=i1-q1*11;
                l1=((sv>>s1)&1u)?(qll[q1]+kl[s1]+bw):(-1e30f); }
            float mx=fmaxf(l0,l1);
            #pragma unroll
            for(int o=16;o>0;o>>=1) mx=fmaxf(mx,__shfl_xor_sync(0xffffffffu,mx,o));
            float e0=(l0>-1e29f)?__expf(l0-mx):0.f;
            float e1=(l1>-1e29f)?__expf(l1-mx):0.f;
            float den=e0+e1;
            float num=e0*gd[i0]+((i1<55)?e1*gd[i1]:0.f);
            #pragma unroll
            for(int o=16;o>0;o>>=1){
                den+=__shfl_xor_sync(0xffffffffu,den,o);
                num+=__shfl_xor_sync(0xffffffffu,num,o);
            }
            if(tid==0) out[b*Tt+t+1]=fsig(__fdividef(num,den));
        }
        __syncthreads();
    }
}

extern "C" void kernel_launch(void* const* d_in, const int* in_sizes, int n_in,
                              void* d_out, int out_size)
{
    const int* user     =(const int*)d_in[0];
    const int* question =(const int*)d_in[1];
    const int* response =(const int*)d_in[2];
    const int* mask     =(const int*)d_in[3];
    const int* qnb      =(const int*)d_in[4];
    const int* snb      =(const int*)d_in[5];
    const int* unb      =(const int*)d_in[6];
    const int* qnb2     =(const int*)d_in[7];
    const int* qsix     =(const int*)d_in[8];
    const float* Eq  =(const float*)d_in[9];
    const float* Eq2 =(const float*)d_in[10];
    const float* Es  =(const float*)d_in[11];
    const float* Eu  =(const float*)d_in[12];
    const float* Er  =(const float*)d_in[13];
    const float* w1q =(const float*)d_in[14];
    const float* w2q =(const float*)d_in[15];
    const float* Wih =(const float*)d_in[16];
    const float* Whh =(const float*)d_in[17];
    const float* bih =(const float*)d_in[18];
    const float* bhh =(const float*)d_in[19];
    const float* aggw=(const float*)d_in[20];
    const float* aggb=(const float*)d_in[21];
    const float* Wal =(const float*)d_in[22];
    const float* bal =(const float*)d_in[23];
    const float* Wq  =(const float*)d_in[24];
    const float* bq  =(const float*)d_in[25];
    const float* Wk  =(const float*)d_in[26];
    const float* bk  =(const float*)d_in[27];
    const float* Ww  =(const float*)d_in[28];
    const float* bw  =(const float*)d_in[29];
    const float* Wfus=(const float*)d_in[30];
    const float* bfus=(const float*)d_in[31];
    float* out=(float*)d_out;

    static int attr_set = 0;
    if(!attr_set){
        cudaFuncSetAttribute(kA, cudaFuncAttributeMaxDynamicSharedMemorySize, DYN_BYTES);
        attr_set = 1;
    }

    prep<<<256,256>>>(aggw,Wal,Wfus,Wih,Whh,bih,bhh,Wq,bq,Wk,bk,Ww);
    kA<<<dim3(TS,Bb),256,DYN_BYTES>>>(user,question,response,mask,qnb,snb,unb,qnb2,qsix,
                            Eq,Eq2,Es,Eu,Er,w1q,w2q,aggb,bal,bfus);
    kB<<<Bb,256>>>(mask,bw,out);
}

// round 14
// speedup vs baseline: 1.7351x; 1.7351x over previous
#include <cuda_runtime.h>
#include <math.h>

#define Bb 32
#define Tt 50
#define TS 49
#define Dd 100
#define G4 400
#define Kk 10

__device__ __align__(16) float g_WTa[3*Dd*Dd];
__device__ __align__(16) float g_WTl[Dd*Dd];
__device__ __align__(16) float g_WTf[2*Dd*Dd];
__device__ __align__(16) float g_WTih[Dd*G4];
__device__ __align__(16) float g_WThh[Dd*G4];
__device__ __align__(16) float g_bsum[G4];
__device__ __align__(16) float g_qvec[Dd];
__device__ __align__(16) float g_kvec[Dd];
__device__ float g_qkb[2];
__device__ __align__(16) float g_gx[Bb*TS*G4];
__device__ __align__(16) float g_qsv[Bb*TS*5*Dd];
__device__ float g_ql[Bb*TS*5];
__device__ int g_ti[Bb*TS*Kk];
__device__ unsigned g_sv[Bb*TS];

__device__ __forceinline__ float ftanh(float x){
    x = fminf(fmaxf(x, -15.0f), 15.0f);
    float e = __expf(-2.0f*x);
    return __fdividef(1.0f - e, 1.0f + e);
}
__device__ __forceinline__ float fsig(float x){
    return __fdividef(1.0f, 1.0f + __expf(-x));
}

__global__ void prep(const float* __restrict__ aggw, const float* __restrict__ Wal,
                     const float* __restrict__ Wfus, const float* __restrict__ Wih,
                     const float* __restrict__ Whh, const float* __restrict__ bih,
                     const float* __restrict__ bhh, const float* __restrict__ Wq,
                     const float* __restrict__ bq, const float* __restrict__ Wk,
                     const float* __restrict__ bk, const float* __restrict__ Ww)
{
    const int N0=3*Dd*Dd, N1=Dd*Dd, N2=2*Dd*Dd, N3=Dd*G4, N4=Dd*G4, N5=G4, N6=Dd, N7=Dd;
    const int total=N0+N1+N2+N3+N4+N5+N6+N7+2;
    for(int i=blockIdx.x*blockDim.x+threadIdx.x; i<total; i+=gridDim.x*blockDim.x){
        int x=i;
        if(x<N0){int j=x/(Dd*Dd);int r=x%(Dd*Dd);int k=r/Dd,d=r%Dd;
            g_WTa[x]=aggw[j*Dd*Dd+d*Dd+k]; continue;}
        x-=N0;
        if(x<N1){int k=x/Dd,d=x%Dd; g_WTl[x]=Wal[d*Dd+k]; continue;}
        x-=N1;
        if(x<N2){int k=x/Dd,d=x%Dd; g_WTf[x]=Wfus[d*2*Dd+k]; continue;}
        x-=N2;
        if(x<N3){int k=x/G4,j=x%G4; g_WTih[x]=Wih[j*Dd+k]; continue;}
        x-=N3;
        if(x<N4){int k=x/G4,j=x%G4; g_WThh[x]=Whh[j*Dd+k]; continue;}
        x-=N4;
        if(x<N5){ g_bsum[x]=bih[x]+bhh[x]; continue;}
        x-=N5;
        if(x<N6){ float a=0.f; for(int j=0;j<Dd;j++) a=fmaf(Wq[j*Dd+x],Ww[j],a);
            g_qvec[x]=a; continue;}
        x-=N6;
        if(x<N7){ float a=0.f; for(int j=0;j<Dd;j++) a=fmaf(Wk[j*Dd+x],Ww[Dd+j],a);
            g_kvec[x]=a; continue;}
        x-=N7;
        if(x==0){ float a=0.f; for(int j=0;j<Dd;j++) a=fmaf(bq[j],Ww[j],a); g_qkb[0]=a; }
        else    { float a=0.f; for(int j=0;j<Dd;j++) a=fmaf(bk[j],Ww[Dd+j],a); g_qkb[1]=a; }
    }
}

struct __align__(16) SB {
    float A2[36][104];
    float A1[6][104];
    float A0[104];
    float s0[104];
    float sTall[Dd][40];
    int L1[8]; int L2[36]; int L3[216];
};
#define DYN_BYTES (2*(int)sizeof(SB))

__device__ __forceinline__ void mv1(const float* s, const float* __restrict__ WT,
                                    const float* __restrict__ bias, float* dst, int lt)
{
    if(lt<Dd){
        float a0=bias[lt],a1=0.f,a2=0.f,a3=0.f;
        #pragma unroll
        for(int k=0;k<Dd;k+=4){
            a0=fmaf(s[k  ],WT[(k  )*Dd+lt],a0);
            a1=fmaf(s[k+1],WT[(k+1)*Dd+lt],a1);
            a2=fmaf(s[k+2],WT[(k+2)*Dd+lt],a2);
            a3=fmaf(s[k+3],WT[(k+3)*Dd+lt],a3);
        }
        dst[lt]=ftanh((a0+a1)+(a2+a3));
    }
}

__device__ __forceinline__ void mv6(const float (*sT)[40], const float* __restrict__ WT,
                                    const float* __restrict__ bias, float (*dst)[104], int lt)
{
    if(lt<Dd){
        float bb=bias[lt];
        float a0=bb,a1=bb,a2=bb,a3=bb,a4=bb,a5=bb;
        #pragma unroll 10
        for(int k=0;k<Dd;k++){
            float w=WT[k*Dd+lt];
            float4 v=*(const float4*)&sT[k][0];
            float2 u=*(const float2*)&sT[k][4];
            a0=fmaf(v.x,w,a0); a1=fmaf(v.y,w,a1); a2=fmaf(v.z,w,a2);
            a3=fmaf(v.w,w,a3); a4=fmaf(u.x,w,a4); a5=fmaf(u.y,w,a5);
        }
        dst[0][lt]=ftanh(a0); dst[1][lt]=ftanh(a1); dst[2][lt]=ftanh(a2);
        dst[3][lt]=ftanh(a3); dst[4][lt]=ftanh(a4); dst[5][lt]=ftanh(a5);
    }
}

// All 36 rows at once: each weight load feeds 36 FMAs.
__device__ __forceinline__ void mv36(const float (*sT)[40], const float* __restrict__ WT,
                                     const float* __restrict__ bias, float (*dst)[104], int lt)
{
    if(lt<Dd){
        float a[36];
        #pragma unroll
        for(int r=0;r<36;r++) a[r]=0.f;
        #pragma unroll 2
        for(int k=0;k<Dd;k++){
            float w=WT[k*Dd+lt];
            #pragma unroll
            for(int rr=0;rr<36;rr+=4){
                float4 v=*(const float4*)&sT[k][rr];
                a[rr  ]=fmaf(v.x,w,a[rr  ]); a[rr+1]=fmaf(v.y,w,a[rr+1]);
                a[rr+2]=fmaf(v.z,w,a[rr+2]); a[rr+3]=fmaf(v.w,w,a[rr+3]);
            }
        }
        float bb=bias[lt];
        #pragma unroll
        for(int r=0;r<36;r++) dst[r][lt]=ftanh(bb+a[r]);
    }
}

// One aggregation side; all 256 threads enter (barriers uniform). lt = tid&127.
__device__ void agg(int n0, const int* __restrict__ tA, const int* __restrict__ tB,
                    const float* __restrict__ Eev, const float* __restrict__ Eod,
                    const float* __restrict__ aggb, const float* __restrict__ bal,
                    SB* Bf, int lt)
{
    const float* W0=g_WTa; const float* W1=g_WTa+Dd*Dd; const float* W2=g_WTa+2*Dd*Dd;
    const float *b0=aggb, *b1=aggb+Dd, *b2=aggb+2*Dd;
    const float inv6=1.0f/6.0f;

    if(lt<6)  Bf->L1[lt]=tA[n0*6+lt];
    if(lt<Dd) Bf->A0[lt]=Eev[(long)n0*Dd+lt];
    __syncthreads();
    if(lt<36) Bf->L2[lt]=tB[Bf->L1[lt/6]*6+lt%6];
    #pragma unroll
    for(int r=0;r<6;r++) if(lt<Dd) Bf->A1[r][lt]=Eod[(long)Bf->L1[r]*Dd+lt];
    __syncthreads();
    for(int r=0;r<36;r++) if(lt<Dd) Bf->A2[r][lt]=Eev[(long)Bf->L2[r]*Dd+lt];
    for(int i=lt;i<216;i+=128) Bf->L3[i]=tA[Bf->L2[i/6]*6+i%6];
    __syncthreads();

    // i=0, j=0 (original A1)
    if(lt<Dd){ float ss=0.f;
        #pragma unroll
        for(int r=0;r<6;r++) ss+=Bf->A1[r][lt];
        Bf->s0[lt]=ss*inv6+Bf->A0[lt]; }
    __syncthreads(); mv1(Bf->s0,W0,b0,Bf->A0,lt); __syncthreads();
    // i=0, j=1 (original A2)
    for(int it=lt;it<600;it+=128){ int g=it/Dd,k=it-g*Dd; float ss=0.f;
        #pragma unroll
        for(int j=0;j<6;j++) ss+=Bf->A2[g*6+j][k];
        Bf->sTall[k][g]=ss*inv6+Bf->A1[g][k]; }
    __syncthreads(); mv6(Bf->sTall,W1,b1,Bf->A1,lt); __syncthreads();
    // i=0, j=2 : all 36 rows in one pass
    for(int it=lt;it<3600;it+=128){
        int r=it/Dd, k=it-r*Dd; float ss=0.f;
        #pragma unroll
        for(int j=0;j<6;j++) ss+=Eod[(long)Bf->L3[r*6+j]*Dd+k];
        Bf->sTall[k][r]=ss*inv6+Bf->A2[r][k];
    }
    __syncthreads(); mv36(Bf->sTall,W2,b2,Bf->A2,lt); __syncthreads();
    // i=1, j=0
    if(lt<Dd){ float ss=0.f;
        #pragma unroll
        for(int r=0;r<6;r++) ss+=Bf->A1[r][lt];
        Bf->s0[lt]=ss*inv6+Bf->A0[lt]; }
    __syncthreads(); mv1(Bf->s0,W0,b0,Bf->A0,lt); __syncthreads();
    // i=1, j=1
    for(int it=lt;it<600;it+=128){ int g=it/Dd,k=it-g*Dd; float ss=0.f;
        #pragma unroll
        for(int j=0;j<6;j++) ss+=Bf->A2[g*6+j][k];
        Bf->sTall[k][g]=ss*inv6+Bf->A1[g][k]; }
    __syncthreads(); mv6(Bf->sTall,W1,b1,Bf->A1,lt); __syncthreads();
    // i=2, j=0
    if(lt<Dd){ float ss=0.f;
        #pragma unroll
        for(int r=0;r<6;r++) ss+=Bf->A1[r][lt];
        Bf->s0[lt]=ss*inv6+Bf->A0[lt]; }
    __syncthreads(); mv1(Bf->s0,W0,b0,Bf->A0,lt); __syncthreads();
    // final projection -> s0 (serves as e1s/e2s)
    mv1(Bf->A0,g_WTl,bal,Bf->s0,lt); __syncthreads();
}

__global__ void __launch_bounds__(256,3) kA(
    const int* __restrict__ user, const int* __restrict__ question,
    const int* __restrict__ response, const int* __restrict__ mask,
    const int* __restrict__ qnb, const int* __restrict__ snb,
    const int* __restrict__ unb, const int* __restrict__ qnb2, const int* __restrict__ qsix,
    const float* __restrict__ Eq, const float* __restrict__ Eq2, const float* __restrict__ Es,
    const float* __restrict__ Eu, const float* __restrict__ Er,
    const float* __restrict__ w1q, const float* __restrict__ w2q,
    const float* __restrict__ aggb, const float* __restrict__ bal,
    const float* __restrict__ bfus)
{
    extern __shared__ __align__(16) float dyn[];
    SB* sbp = (SB*)dyn;
    __shared__ float sc[64];

    int t=blockIdx.x, b=blockIdx.y, tid=threadIdx.x;
    int side=tid>>7, lt=tid&127;
    int qt=question[b*Tt+t], ut=user[b*Tt+t], rt=response[b*Tt+t], m=mask[b*Tt+t];

    if(m==1){
        int n0            = side ? ut   : qt;
        const int* tA     = side ? unb  : qnb;
        const int* tB     = side ? qnb2 : snb;
        const float* Eev  = side ? Eu   : Eq;
        const float* Eod  = side ? Eq2  : Es;
        agg(n0,tA,tB,Eev,Eod,aggb,bal,&sbp[side],lt);
    } else {
        if(tid<Dd){
            sbp[0].s0[tid]=Eq[(long)qt*Dd+tid];
            sbp[1].s0[tid]=Eq2[(long)qt*Dd+tid];
        }
    }
    __syncthreads();

    // scratch overlays (post-agg)
    float* e1s=sbp[0].s0;  float* e2s=sbp[1].s0;
    float* eh =(float*)sbp[0].A1;  float* erv=eh+104;  float* etv=eh+208;
    float* qss=(float*)sbp[1].A1;

    float w1=w1q[0], w2=w2q[0];
    if(tid<Dd){ eh[tid]=w1*e1s[tid]+w2*e2s[tid]; erv[tid]=Er[rt*Dd+tid]; }
    __syncthreads();
    if(tid<Dd){
        float a=bfus[tid];
        #pragma unroll 4
        for(int k=0;k<Dd;k++) a=fmaf(eh[k],g_WTf[k*Dd+tid],a);
        #pragma unroll 4
        for(int k=0;k<Dd;k++) a=fmaf(erv[k],g_WTf[(Dd+k)*Dd+tid],a);
        etv[tid]=fmaxf(a,0.0f);
    }
    __syncthreads();

    long bt=(long)b*TS+t;
    if(tid<200){
        float2 a0=*(const float2*)&g_bsum[2*tid];
        float2 a1=make_float2(0.f,0.f);
        #pragma unroll 4
        for(int k=0;k<Dd;k+=2){
            float2 w0=*(const float2*)&g_WTih[k*G4+2*tid];
            float2 w1v=*(const float2*)&g_WTih[(k+1)*G4+2*tid];
            float e0=etv[k], e1v=etv[k+1];
            a0.x=fmaf(e0,w0.x,a0.x); a0.y=fmaf(e0,w0.y,a0.y);
            a1.x=fmaf(e1v,w1v.x,a1.x); a1.y=fmaf(e1v,w1v.y,a1.y);
        }
        float2 r; r.x=a0.x+a1.x; r.y=a0.y+a1.y;
        *(float2*)&g_gx[bt*G4+2*tid]=r;
    }

    int qn=question[b*Tt+t+1];
    if(tid<Dd){
        qss[tid]=Eq[(long)qn*Dd+tid];
        #pragma unroll
        for(int q=1;q<5;q++){
            int sid=qsix[qn*4+(q-1)];
            qss[q*Dd+tid]=Es[(long)sid*Dd+tid];
        }
    }
    __syncthreads();
    for(int i=tid;i<5*Dd;i+=256) g_qsv[bt*5*Dd+i]=qss[i];
    if(tid<5){
        float a=g_qkb[0];
        #pragma unroll 4
        for(int d=0;d<Dd;d++) a=fmaf(qss[tid*Dd+d],g_qvec[d],a);
        g_ql[bt*5+tid]=a;
    }
    if(tid<t){
        int qj=question[b*Tt+tid];
        const float4* row=(const float4*)(Eq+(long)qj*Dd);
        float a=0.f;
        #pragma unroll 5
        for(int kk=0;kk<25;kk++){
            float4 r4=row[kk];
            a=fmaf(r4.x,qss[4*kk+0],a); a=fmaf(r4.y,qss[4*kk+1],a);
            a=fmaf(r4.z,qss[4*kk+2],a); a=fmaf(r4.w,qss[4*kk+3],a);
        }
        sc[tid]=a;
    }
    __syncthreads();
    if(tid==0){
        unsigned sv=1u;
        bool used[64];
        for(int j=0;j<t;j++) used[j]=false;
        for(int s=0;s<Kk;s++){
            float best=-3.4e38f; int bi=-1;
            for(int j=0;j<t;j++)
                if(!used[j] && sc[j]>best){ best=sc[j]; bi=j; }
            if(bi>=0){ used[bi]=true; g_ti[bt*Kk+s]=bi; sv|=(1u<<(s+1)); }
            else      { g_ti[bt*Kk+s]=0; }
        }
        g_sv[bt]=sv;
    }
}

__global__ void __launch_bounds__(256) kB(const int* __restrict__ mask,
                                          const float* __restrict__ bw_,
                                          float* __restrict__ out)
{
    __shared__ float h[104], c[104];
    __shared__ __align__(16) float gates[G4];
    __shared__ float sh[TS][Dd];
    __shared__ __align__(16) float qsl[5*Dd];
    __shared__ float gd[56], kl[12], qll[8], kv[104];
    __shared__ int il[12];
    __shared__ unsigned sv_s;

    int b=blockIdx.x, tid=threadIdx.x;
    if(tid<Dd){ h[tid]=0.f; c[tid]=0.f; kv[tid]=g_kvec[tid]; }
    if(tid==0) out[b*Tt]=0.5f;
    __syncthreads();
    float kb=g_qkb[1], bw=bw_[0];

    for(int t=0;t<TS;t++){
        long bt=(long)b*TS+t;
        if(tid<200){
            float2 a0=*(const float2*)&g_gx[bt*G4+2*tid];
            float2 a1=make_float2(0.f,0.f);
            float2 a2=make_float2(0.f,0.f);
            float2 a3=make_float2(0.f,0.f);
            #pragma unroll 4
            for(int k=0;k<Dd;k+=4){
                float h0=h[k],h1=h[k+1],h2=h[k+2],h3=h[k+3];
                float2 w0=*(const float2*)&g_WThh[(k  )*G4+2*tid];
                float2 w1=*(const float2*)&g_WThh[(k+1)*G4+2*tid];
                float2 w2=*(const float2*)&g_WThh[(k+2)*G4+2*tid];
                float2 w3=*(const float2*)&g_WThh[(k+3)*G4+2*tid];
                a0.x=fmaf(h0,w0.x,a0.x); a0.y=fmaf(h0,w0.y,a0.y);
                a1.x=fmaf(h1,w1.x,a1.x); a1.y=fmaf(h1,w1.y,a1.y);
                a2.x=fmaf(h2,w2.x,a2.x); a2.y=fmaf(h2,w2.y,a2.y);
                a3.x=fmaf(h3,w3.x,a3.x); a3.y=fmaf(h3,w3.y,a3.y);
            }
            float2 r; r.x=(a0.x+a1.x)+(a2.x+a3.x); r.y=(a0.y+a1.y)+(a2.y+a3.y);
            *(float2*)&gates[2*tid]=r;
        }
        __syncthreads();
        if(tid<Dd){
            float gi=gates[tid], gf=gates[Dd+tid], gg=gates[2*Dd+tid], go=gates[3*Dd+tid];
            float c2=fsig(gf)*c[tid]+fsig(gi)*ftanh(gg);
            float h2=fsig(go)*ftanh(c2);
            if(mask[b*Tt+t]==1){ h[tid]=h2; c[tid]=c2; }
            sh[t][tid]=h[tid];
        }
        for(int i=tid;i<5*Dd;i+=256) qsl[i]=g_qsv[bt*5*Dd+i];
        if(tid>=128&&tid<138) il[tid-128]=g_ti[bt*Kk+tid-128];
        if(tid>=138&&tid<143) qll[tid-138]=g_ql[bt*5+tid-138];
        if(tid==143) sv_s=g_sv[bt];
        __syncthreads();
        if(tid<55){
            int q=tid/11, s=tid-q*11;
            const float* st=(s==0)?h:sh[il[s-1]];
            float a0=0.f,a1=0.f;
            #pragma unroll 2
            for(int d=0;d<Dd;d+=2){
                a0=fmaf(qsl[q*Dd+d],st[d],a0);
                a1=fmaf(qsl[q*Dd+d+1],st[d+1],a1);
            }
            gd[tid]=a0+a1;
        }
        if(tid>=64&&tid<75){
            int s=tid-64;
            const float* st=(s==0)?h:sh[il[s-1]];
            float a0=kb,a1=0.f;
            #pragma unroll 2
            for(int d=0;d<Dd;d+=2){
                a0=fmaf(st[d],kv[d],a0);
                a1=fmaf(st[d+1],kv[d+1],a1);
            }
            kl[s]=a0+a1;
        }
        __syncthreads();
        if(tid<32){
            unsigned sv=sv_s;
            int i0=tid, i1=tid+32;
            int q0=i0/11, s0=i0-q0*11;
            float l0=((sv>>s0)&1u)?(qll[q0]+kl[s0]+bw):(-1e30f);
            float l1=-1e30f;
            if(i1<55){ int q1=i1/11, s1=i1-q1*11;
                l1=((sv>>s1)&1u)?(qll[q1]+kl[s1]+bw):(-1e30f); }
            float mx=fmaxf(l0,l1);
            #pragma unroll
            for(int o=16;o>0;o>>=1) mx=fmaxf(mx,__shfl_xor_sync(0xffffffffu,mx,o));
            float e0=(l0>-1e29f)?__expf(l0-mx):0.f;
            float e1=(l1>-1e29f)?__expf(l1-mx):0.f;
            float den=e0+e1;
            float num=e0*gd[i0]+((i1<55)?e1*gd[i1]:0.f);
            #pragma unroll
            for(int o=16;o>0;o>>=1){
                den+=__shfl_xor_sync(0xffffffffu,den,o);
                num+=__shfl_xor_sync(0xffffffffu,num,o);
            }
            if(tid==0) out[b*Tt+t+1]=fsig(__fdividef(num,den));
        }
        __syncthreads();
    }
}

extern "C" void kernel_launch(void* const* d_in, const int* in_sizes, int n_in,
                              void* d_out, int out_size)
{
    const int* user     =(const int*)d_in[0];
    const int* question =(const int*)d_in[1];
    const int* response =(const int*)d_in[2];
    const int* mask     =(const int*)d_in[3];
    const int* qnb      =(const int*)d_in[4];
    const int* snb      =(const int*)d_in[5];
    const int* unb      =(const int*)d_in[6];
    const int* qnb2     =(const int*)d_in[7];
    const int* qsix     =(const int*)d_in[8];
    const float* Eq  =(const float*)d_in[9];
    const float* Eq2 =(const float*)d_in[10];
    const float* Es  =(const float*)d_in[11];
    const float* Eu  =(const float*)d_in[12];
    const float* Er  =(const float*)d_in[13];
    const float* w1q =(const float*)d_in[14];
    const float* w2q =(const float*)d_in[15];
    const float* Wih =(const float*)d_in[16];
    const float* Whh =(const float*)d_in[17];
    const float* bih =(const float*)d_in[18];
    const float* bhh =(const float*)d_in[19];
    const float* aggw=(const float*)d_in[20];
    const float* aggb=(const float*)d_in[21];
    const float* Wal =(const float*)d_in[22];
    const float* bal =(const float*)d_in[23];
    const float* Wq  =(const float*)d_in[24];
    const float* bq  =(const float*)d_in[25];
    const float* Wk  =(const float*)d_in[26];
    const float* bk  =(const float*)d_in[27];
    const float* Ww  =(const float*)d_in[28];
    const float* bw  =(const float*)d_in[29];
    const float* Wfus=(const float*)d_in[30];
    const float* bfus=(const float*)d_in[31];
    float* out=(float*)d_out;

    static int attr_set = 0;
    if(!attr_set){
        cudaFuncSetAttribute(kA, cudaFuncAttributeMaxDynamicSharedMemorySize, DYN_BYTES);
        attr_set = 1;
    }

    prep<<<256,256>>>(aggw,Wal,Wfus,Wih,Whh,bih,bhh,Wq,bq,Wk,bk,Ww);
    kA<<<dim3(TS,Bb),256,DYN_BYTES>>>(user,question,response,mask,qnb,snb,unb,qnb2,qsix,
                            Eq,Eq2,Es,Eu,Er,w1q,w2q,aggb,bal,bfus);
    kB<<<Bb,256>>>(mask,bw,out);
}